// round 2
// baseline (speedup 1.0000x reference)
#include <cuda_runtime.h>
#include <math.h>

#define NPFS  4
#define NF    512
#define NP    256
#define BATCH 128
#define NMAT  (BATCH * NPFS)            // 512 matrices
#define TRI_ELEMS ((NP * (NP - 1)) / 2) // 32640
#define NTHR  512
#define NW    (NTHR / 32)               // 16 warps

// Scratch (__device__ globals — allocations forbidden)
__device__ float g_Ffull[NPFS * NF * NF];   // antisymmetrized F, 4 MB (L2-resident)
__device__ float g_sign[NMAT];
__device__ float g_logabs[NMAT];

__device__ __forceinline__ unsigned tri(int r) {
    return ((unsigned)(r * (r - 1))) >> 1;   // base of row r in lower triangle
}

// ---------------------------------------------------------------------------
// Kernel 1: F_full = 0.5 * (F - F^T)
// ---------------------------------------------------------------------------
__global__ void prep_kernel(const float* __restrict__ F) {
    int i = blockIdx.x * 256 + threadIdx.x;
    int p   = i >> 18;
    int rem = i & ((1 << 18) - 1);
    int r = rem >> 9;
    int c = rem & (NF - 1);
    float a = F[i];
    float b = F[(p << 18) + (c << 9) + r];
    g_Ffull[i] = 0.5f * (a - b);
}

// ---------------------------------------------------------------------------
// Kernel 2: one CTA per matrix. Lower triangle in smem; Parlett-Reid with
// partial pivoting. Swap fused into tau/v fill (dead row/col k+1 never
// written); rank-2 update vectorized (LDS.128 row, LDS.64 interleaved tau/v).
// ---------------------------------------------------------------------------
__global__ __launch_bounds__(NTHR, 1)
void pf_kernel(const int* __restrict__ idx) {
    extern __shared__ float sm[];
    float* L  = sm;                 // [TRI_ELEMS]  L[tri(r)+c] = A[r][c], r>c
    float* tv = sm + TRI_ELEMS;     // [2*NP] interleaved {tau, v}

    __shared__ int   s_idx[NP];
    __shared__ float s_rv[NW];
    __shared__ int   s_ri[NW];

    const int tid  = threadIdx.x;
    const int lane = tid & 31;
    const int wid  = tid >> 5;
    const int m    = blockIdx.x;
    const int b    = m >> 2;
    const int p    = m & 3;

    if (tid < NP) s_idx[tid] = idx[b * NP + tid];
    __syncthreads();

    // ---- gather: L[r][c] = Ffull[p][idx[r]][idx[c]], r > c (warp per row) ----
    {
        const float* Fp = g_Ffull + (size_t)p * (NF * NF);
        for (int r = wid; r < NP; r += NW) {
            const float* row = Fp + (size_t)s_idx[r] * NF;
            unsigned base = tri(r);
            for (int c = lane; c < r; c += 32)
                L[base + c] = __ldg(&row[s_idx[c]]);
        }
    }
    __syncthreads();

    float sign = 1.f, logabs = 0.f;   // live in thread 0

    for (int k = 0; k < NP; k += 2) {
        const int p1 = k + 1;
        const int k2 = k + 2;

        // ---- phase 1: pivot search argmax_{r>k} |A[r][k]| ----
        float bv = -1.f; int bi = NP;
        if (tid > k && tid < NP) { bv = fabsf(L[tri(tid) + k]); bi = tid; }
        #pragma unroll
        for (int off = 16; off; off >>= 1) {
            float ov = __shfl_down_sync(0xffffffffu, bv, off);
            int   oi = __shfl_down_sync(0xffffffffu, bi, off);
            if (ov > bv || (ov == bv && oi < bi)) { bv = ov; bi = oi; }
        }
        if (lane == 0) { s_rv[wid] = bv; s_ri[wid] = bi; }
        __syncthreads();
        bv = s_rv[0]; bi = s_ri[0];
        #pragma unroll
        for (int w = 1; w < NW; w++) {
            float ov = s_rv[w]; int oi = s_ri[w];
            if (ov > bv || (ov == bv && oi < bi)) { bv = ov; bi = oi; }
        }
        const int kp = bi;   // pivot row in (k, NP)

        // post-swap pivot A[k][k+1] = A_old[k][kp] = -L[tri(kp)+k]  (broadcast)
        const float piv = -L[tri(kp) + k];
        if (tid == 0) {
            if (kp != p1)  sign = -sign;
            if (piv < 0.f) sign = -sign;
            logabs += logf(fabsf(piv));
        }

        // ---- phase 2: fused tau/v fill + live half of the swap ----
        // Dead region (row/col p1, col k) is never written; row/col kp gets
        // old p1 values. Race-free: sources are dead locations.
        if (tid >= k2 && tid < NP) {
            const int t = tid;
            const float rp = 1.0f / piv;
            float tauv, vv;
            if (kp != p1) {
                tauv = (t == kp ? L[tri(p1) + k] : L[tri(t) + k]) * rp;
                if (t < kp) {
                    vv = -L[tri(kp) + t];
                    L[tri(kp) + t] = -L[tri(t) + p1];
                } else if (t == kp) {
                    vv = -L[tri(kp) + p1];
                } else {
                    vv = L[tri(t) + kp];
                    L[tri(t) + kp] = L[tri(t) + p1];
                }
            } else {
                tauv = L[tri(t) + k] * rp;
                vv   = L[tri(t) + p1];
            }
            tv[2 * t]     = tauv;
            tv[2 * t + 1] = vv;
        }
        __syncthreads();

        // ---- phase 3: rank-2 update A[r][c] += v_r*tau_c - tau_r*v_c ----
        if (k2 < NP) {
            for (int r = k2 + wid; r < NP; r += NW) {
                const unsigned base = tri(r);
                const float tr = tv[2 * r], vr = tv[2 * r + 1];
                const int cbeg = k2, cend = r;
                if (cend <= cbeg) continue;
                int calign = cbeg + ((-(int)(base + cbeg)) & 3);
                if (calign > cend) calign = cend;
                // scalar head (<4 elems)
                {
                    int c = cbeg + lane;
                    if (c < calign)
                        L[base + c] += vr * tv[2 * c] - tr * tv[2 * c + 1];
                }
                // vector body
                const int nvec = (cend - calign) >> 2;
                for (int q = lane; q < nvec; q += 32) {
                    const int cc = calign + 4 * q;
                    float4 x = *(const float4*)&L[base + cc];
                    float2 a0 = *(const float2*)&tv[2 * cc];
                    float2 a1 = *(const float2*)&tv[2 * cc + 2];
                    float2 a2 = *(const float2*)&tv[2 * cc + 4];
                    float2 a3 = *(const float2*)&tv[2 * cc + 6];
                    x.x += vr * a0.x - tr * a0.y;
                    x.y += vr * a1.x - tr * a1.y;
                    x.z += vr * a2.x - tr * a2.y;
                    x.w += vr * a3.x - tr * a3.y;
                    *(float4*)&L[base + cc] = x;
                }
                // scalar tail (<4 elems)
                {
                    int c = calign + 4 * nvec + lane;
                    if (c < cend)
                        L[base + c] += vr * tv[2 * c] - tr * tv[2 * c + 1];
                }
            }
        }
        __syncthreads();
    }

    if (tid == 0) { g_sign[m] = sign; g_logabs[m] = logabs; }
}

// ---------------------------------------------------------------------------
// Kernel 3: signed logsumexp over the 4 pfaffians per batch element
// ---------------------------------------------------------------------------
__global__ void combine_kernel(float* __restrict__ out) {
    int b = threadIdx.x;
    if (b < BATCH) {
        float la[NPFS], sg[NPFS];
        float mx = -INFINITY;
        #pragma unroll
        for (int p = 0; p < NPFS; p++) {
            la[p] = g_logabs[b * NPFS + p];
            sg[p] = g_sign[b * NPFS + p];
            mx = fmaxf(mx, la[p]);
        }
        float val = 0.f;
        #pragma unroll
        for (int p = 0; p < NPFS; p++)
            val += sg[p] * expf(la[p] - mx);
        out[b]         = (val > 0.f) ? 1.f : ((val < 0.f) ? -1.f : 0.f);
        out[BATCH + b] = mx + logf(fabsf(val));
    }
}

// ---------------------------------------------------------------------------
extern "C" void kernel_launch(void* const* d_in, const int* in_sizes, int n_in,
                              void* d_out, int out_size) {
    const float* F   = (const float*)d_in[0];   // (4, 512, 512) fp32
    const int*   idx = (const int*)  d_in[1];   // (128, 256) int32
    float*       out = (float*)d_out;           // (2, 128) fp32

    const size_t shmem = (size_t)(TRI_ELEMS + 2 * NP) * sizeof(float); // ~132.6 KB
    cudaFuncSetAttribute(pf_kernel, cudaFuncAttributeMaxDynamicSharedMemorySize,
                         (int)shmem);

    prep_kernel<<<(NPFS * NF * NF) / 256, 256>>>(F);
    pf_kernel<<<NMAT, NTHR, shmem>>>(idx);
    combine_kernel<<<1, 128>>>(out);
}

// round 3
// speedup vs baseline: 1.7481x; 1.7481x over previous
#include <cuda_runtime.h>
#include <math.h>

#define NPFS  4
#define NF    512
#define NP    256
#define BATCH 128
#define NMAT  (BATCH * NPFS)            // 512 matrices
#define NTHR  512
#define NW    (NTHR / 32)               // 16 warps

// padded, 16B-aligned row bases for the lower triangle
__device__ __host__ __forceinline__ unsigned rowb(int r) {
    return ((unsigned)((r * (r - 1)) / 2 + 6 * r)) & ~3u;
}
#define L_ELEMS 34176                    // >= rowb(255) + 260, mult of 4

// Scratch (__device__ globals — allocations forbidden)
__device__ float g_Ffull[NPFS * NF * NF];   // antisymmetrized F, 4 MB (L2-resident)
__device__ float g_sign[NMAT];
__device__ float g_logabs[NMAT];

// ---------------------------------------------------------------------------
// Kernel 1: F_full = 0.5 * (F - F^T)
// ---------------------------------------------------------------------------
__global__ void prep_kernel(const float* __restrict__ F) {
    int i = blockIdx.x * 256 + threadIdx.x;
    int p   = i >> 18;
    int rem = i & ((1 << 18) - 1);
    int r = rem >> 9;
    int c = rem & (NF - 1);
    float a = F[i];
    float b = F[(p << 18) + (c << 9) + r];
    g_Ffull[i] = 0.5f * (a - b);
}

__device__ __forceinline__ void wred(float& bv, int& bi) {
    #pragma unroll
    for (int off = 16; off; off >>= 1) {
        float ov = __shfl_down_sync(0xffffffffu, bv, off);
        int   oi = __shfl_down_sync(0xffffffffu, bi, off);
        if (ov > bv || (ov == bv && oi < bi)) { bv = ov; bi = oi; }
    }
}

// ---------------------------------------------------------------------------
// Kernel 2: one CTA per matrix. Lower triangle (aligned padded rows) in smem.
// Parlett-Reid, partial pivoting. Swap fused into tau/v fill; pivot search
// for step k+2 fused into step k's rank-2 update. All smem ops 128-bit,
// conflict-free. 2 barriers per step.
// ---------------------------------------------------------------------------
__global__ __launch_bounds__(NTHR, 1)
void pf_kernel(const int* __restrict__ idx) {
    extern __shared__ float sm[];
    float* L   = sm;                 // [L_ELEMS]
    float* tau = sm + L_ELEMS;       // [NP]
    float* v   = tau + NP;           // [NP]

    __shared__ int   s_idx[NP];
    __shared__ float s_rv[NW];
    __shared__ int   s_ri[NW];

    const int tid  = threadIdx.x;
    const int lane = tid & 31;
    const int wid  = tid >> 5;
    const int m    = blockIdx.x;
    const int b    = m >> 2;
    const int p    = m & 3;

    if (tid < NP) s_idx[tid] = idx[b * NP + tid];
    __syncthreads();

    // ---- gather (warp per row) + initial pivot scan of column 0 ----
    {
        float bv = -1.f; int bi = NP;
        const float* Fp = g_Ffull + (size_t)p * (NF * NF);
        for (int r = wid; r < NP; r += NW) {
            const float* row = Fp + (size_t)s_idx[r] * NF;
            unsigned base = rowb(r);
            for (int c = lane; c < r; c += 32) {
                float val = __ldg(&row[s_idx[c]]);
                L[base + c] = val;
                if (c == 0) {
                    float a = fabsf(val);
                    if (a > bv || (a == bv && r < bi)) { bv = a; bi = r; }
                }
            }
        }
        wred(bv, bi);
        if (lane == 0) { s_rv[wid] = bv; s_ri[wid] = bi; }
    }
    __syncthreads();

    float sign = 1.f, logabs = 0.f;   // live in thread 0

    for (int k = 0; k < NP; k += 2) {
        const int p1 = k + 1;
        const int k2 = k + 2;

        // ---- reduce the NW pivot candidates (all threads, 16-lane butterfly) ----
        float pv = s_rv[lane & (NW - 1)];
        int   pi = s_ri[lane & (NW - 1)];
        #pragma unroll
        for (int off = NW / 2; off; off >>= 1) {
            float ov = __shfl_xor_sync(0xffffffffu, pv, off);
            int   oi = __shfl_xor_sync(0xffffffffu, pi, off);
            if (ov > pv || (ov == pv && oi < pi)) { pv = ov; pi = oi; }
        }
        const int kp = pi;                         // pivot row in (k, NP)
        const float piv = -L[rowb(kp) + k];        // post-swap A[k][k+1]
        if (tid == 0) {
            if (kp != p1)  sign = -sign;
            if (piv < 0.f) sign = -sign;
            logabs += logf(fabsf(piv));
        }

        // ---- fill tau/v (zeros at k, k+1) + live half of the symmetric swap ----
        if (tid >= k && tid < NP) {
            const int t = tid;
            float tauv = 0.f, vv = 0.f;
            if (t >= k2) {
                const float rp = 1.0f / piv;
                if (kp != p1) {
                    tauv = (t == kp ? L[rowb(p1) + k] : L[rowb(t) + k]) * rp;
                    if (t < kp) {
                        vv = -L[rowb(kp) + t];
                        L[rowb(kp) + t] = -L[rowb(t) + p1];
                    } else if (t == kp) {
                        vv = -L[rowb(kp) + p1];
                    } else {
                        vv = L[rowb(t) + kp];
                        L[rowb(t) + kp] = L[rowb(t) + p1];
                    }
                } else {
                    tauv = L[rowb(t) + k] * rp;
                    vv   = L[rowb(t) + p1];
                }
            }
            tau[t] = tauv;
            v[t]   = vv;
        }
        __syncthreads();

        // ---- rank-2 update (row pairs per warp) + fused scan of column k2 ----
        float bv = -1.f; int bi = NP;
        {
            const int cstart = k & ~3;
            const int k2c    = k2 & ~3;
            const bool hi2   = (k2 & 2) != 0;
            for (int pr = wid; ; pr += NW) {
                const int r0 = k2 + 1 + 2 * pr;
                if (r0 >= NP) break;
                const int r1 = r0 + 1;
                const unsigned b0 = rowb(r0);
                const unsigned b1 = (r1 < NP) ? rowb(r1) : 0u;
                const int e0 = (r0 + 3) & ~3;
                const int e1 = (r1 < NP) ? ((r1 + 3) & ~3) : 0;
                const int emax = (e1 > e0) ? e1 : e0;
                const float tr0 = tau[r0], vr0 = v[r0];
                const float tr1 = (r1 < NP) ? tau[r1] : 0.f;
                const float vr1 = (r1 < NP) ? v[r1]   : 0.f;
                for (int cc = cstart + 4 * lane; cc < emax; cc += 128) {
                    const float4 tc = *(const float4*)&tau[cc];
                    const float4 vc = *(const float4*)&v[cc];
                    float4 x0, x1;
                    const bool a0 = cc < e0;
                    const bool a1 = cc < e1;
                    if (a0) {
                        x0 = *(const float4*)&L[b0 + cc];
                        x0.x += vr0 * tc.x - tr0 * vc.x;
                        x0.y += vr0 * tc.y - tr0 * vc.y;
                        x0.z += vr0 * tc.z - tr0 * vc.z;
                        x0.w += vr0 * tc.w - tr0 * vc.w;
                        *(float4*)&L[b0 + cc] = x0;
                    }
                    if (a1) {
                        x1 = *(const float4*)&L[b1 + cc];
                        x1.x += vr1 * tc.x - tr1 * vc.x;
                        x1.y += vr1 * tc.y - tr1 * vc.y;
                        x1.z += vr1 * tc.z - tr1 * vc.z;
                        x1.w += vr1 * tc.w - tr1 * vc.w;
                        *(float4*)&L[b1 + cc] = x1;
                    }
                    if (cc == k2c) {   // capture next pivot column entries
                        if (a0) {
                            float a = fabsf(hi2 ? x0.z : x0.x);
                            if (a > bv || (a == bv && r0 < bi)) { bv = a; bi = r0; }
                        }
                        if (a1) {
                            float a = fabsf(hi2 ? x1.z : x1.x);
                            if (a > bv || (a == bv && r1 < bi)) { bv = a; bi = r1; }
                        }
                    }
                }
            }
        }
        wred(bv, bi);
        if (lane == 0) { s_rv[wid] = bv; s_ri[wid] = bi; }
        __syncthreads();
    }

    if (tid == 0) { g_sign[m] = sign; g_logabs[m] = logabs; }
}

// ---------------------------------------------------------------------------
// Kernel 3: signed logsumexp over the 4 pfaffians per batch element
// ---------------------------------------------------------------------------
__global__ void combine_kernel(float* __restrict__ out) {
    int b = threadIdx.x;
    if (b < BATCH) {
        float la[NPFS], sg[NPFS];
        float mx = -INFINITY;
        #pragma unroll
        for (int p = 0; p < NPFS; p++) {
            la[p] = g_logabs[b * NPFS + p];
            sg[p] = g_sign[b * NPFS + p];
            mx = fmaxf(mx, la[p]);
        }
        float val = 0.f;
        #pragma unroll
        for (int p = 0; p < NPFS; p++)
            val += sg[p] * expf(la[p] - mx);
        out[b]         = (val > 0.f) ? 1.f : ((val < 0.f) ? -1.f : 0.f);
        out[BATCH + b] = mx + logf(fabsf(val));
    }
}

// ---------------------------------------------------------------------------
extern "C" void kernel_launch(void* const* d_in, const int* in_sizes, int n_in,
                              void* d_out, int out_size) {
    const float* F   = (const float*)d_in[0];   // (4, 512, 512) fp32
    const int*   idx = (const int*)  d_in[1];   // (128, 256) int32
    float*       out = (float*)d_out;           // (2, 128) fp32

    const size_t shmem = (size_t)(L_ELEMS + 2 * NP) * sizeof(float); // ~138.8 KB
    cudaFuncSetAttribute(pf_kernel, cudaFuncAttributeMaxDynamicSharedMemorySize,
                         (int)shmem);

    prep_kernel<<<(NPFS * NF * NF) / 256, 256>>>(F);
    pf_kernel<<<NMAT, NTHR, shmem>>>(idx);
    combine_kernel<<<1, 128>>>(out);
}

// round 4
// speedup vs baseline: 1.7483x; 1.0001x over previous
#include <cuda_runtime.h>
#include <math.h>

#define NPFS  4
#define NF    512
#define NP    256
#define BATCH 128
#define NMAT  (BATCH * NPFS)            // 512 matrices
#define NTHR  512
#define NW    (NTHR / 32)               // 16 warps

// padded, 16B-aligned row bases for the lower triangle
__device__ __host__ __forceinline__ unsigned rowb(int r) {
    return ((unsigned)((r * (r - 1)) / 2 + 6 * r)) & ~3u;
}
#define L_ELEMS 34176                    // >= rowb(255) + 260, mult of 4

// Scratch (__device__ globals — allocations forbidden)
__device__ float g_Ffull[NPFS * NF * NF];   // antisymmetrized F, 4 MB (L2-resident)
__device__ float g_sign[NMAT];
__device__ float g_logabs[NMAT];

// ---------------------------------------------------------------------------
// Kernel 1: F_full = 0.5 * (F - F^T)
// ---------------------------------------------------------------------------
__global__ void prep_kernel(const float* __restrict__ F) {
    int i = blockIdx.x * 256 + threadIdx.x;
    int p   = i >> 18;
    int rem = i & ((1 << 18) - 1);
    int r = rem >> 9;
    int c = rem & (NF - 1);
    float a = F[i];
    float b = F[(p << 18) + (c << 9) + r];
    g_Ffull[i] = 0.5f * (a - b);
}

__device__ __forceinline__ void wred(float& bv, int& bi) {
    #pragma unroll
    for (int off = 16; off; off >>= 1) {
        float ov = __shfl_down_sync(0xffffffffu, bv, off);
        int   oi = __shfl_down_sync(0xffffffffu, bi, off);
        if (ov > bv || (ov == bv && oi < bi)) { bv = ov; bi = oi; }
    }
}

// ---------------------------------------------------------------------------
// Kernel 2: one CTA per matrix. Lower triangle (aligned padded rows) in smem.
// Parlett-Reid, partial pivoting. Swap fused into tau/v fill; pivot search
// for step k+2 fused into step k's rank-2 update. All smem ops 128-bit,
// conflict-free. 2 barriers per step.
// ---------------------------------------------------------------------------
__global__ __launch_bounds__(NTHR, 1)
void pf_kernel(const int* __restrict__ idx) {
    extern __shared__ float sm[];
    float* L   = sm;                 // [L_ELEMS]
    float* tau = sm + L_ELEMS;       // [NP]
    float* v   = tau + NP;           // [NP]

    __shared__ int   s_idx[NP];
    __shared__ float s_rv[NW];
    __shared__ int   s_ri[NW];

    const int tid  = threadIdx.x;
    const int lane = tid & 31;
    const int wid  = tid >> 5;
    const int m    = blockIdx.x;
    const int b    = m >> 2;
    const int p    = m & 3;

    if (tid < NP) s_idx[tid] = idx[b * NP + tid];
    __syncthreads();

    // ---- gather (warp per row) + initial pivot scan of column 0 ----
    {
        float bv = -1.f; int bi = NP;
        const float* Fp = g_Ffull + (size_t)p * (NF * NF);
        for (int r = wid; r < NP; r += NW) {
            const float* row = Fp + (size_t)s_idx[r] * NF;
            unsigned base = rowb(r);
            for (int c = lane; c < r; c += 32) {
                float val = __ldg(&row[s_idx[c]]);
                L[base + c] = val;
                if (c == 0) {
                    float a = fabsf(val);
                    if (a > bv || (a == bv && r < bi)) { bv = a; bi = r; }
                }
            }
        }
        wred(bv, bi);
        if (lane == 0) { s_rv[wid] = bv; s_ri[wid] = bi; }
    }
    __syncthreads();

    float sign = 1.f, logabs = 0.f;   // live in thread 0

    for (int k = 0; k < NP; k += 2) {
        const int p1 = k + 1;
        const int k2 = k + 2;

        // ---- reduce the NW pivot candidates (all threads, 16-lane butterfly) ----
        float pv = s_rv[lane & (NW - 1)];
        int   pi = s_ri[lane & (NW - 1)];
        #pragma unroll
        for (int off = NW / 2; off; off >>= 1) {
            float ov = __shfl_xor_sync(0xffffffffu, pv, off);
            int   oi = __shfl_xor_sync(0xffffffffu, pi, off);
            if (ov > pv || (ov == pv && oi < pi)) { pv = ov; pi = oi; }
        }
        const int kp = pi;                         // pivot row in (k, NP)
        const float piv = -L[rowb(kp) + k];        // post-swap A[k][k+1]
        if (tid == 0) {
            if (kp != p1)  sign = -sign;
            if (piv < 0.f) sign = -sign;
            logabs += logf(fabsf(piv));
        }

        // ---- fill tau/v (zeros at k, k+1) + live half of the symmetric swap ----
        if (tid >= k && tid < NP) {
            const int t = tid;
            float tauv = 0.f, vv = 0.f;
            if (t >= k2) {
                const float rp = 1.0f / piv;
                if (kp != p1) {
                    tauv = (t == kp ? L[rowb(p1) + k] : L[rowb(t) + k]) * rp;
                    if (t < kp) {
                        vv = -L[rowb(kp) + t];
                        L[rowb(kp) + t] = -L[rowb(t) + p1];
                    } else if (t == kp) {
                        vv = -L[rowb(kp) + p1];
                    } else {
                        vv = L[rowb(t) + kp];
                        L[rowb(t) + kp] = L[rowb(t) + p1];
                    }
                } else {
                    tauv = L[rowb(t) + k] * rp;
                    vv   = L[rowb(t) + p1];
                }
            }
            tau[t] = tauv;
            v[t]   = vv;
        }
        __syncthreads();

        // ---- rank-2 update (row pairs per warp) + fused scan of column k2 ----
        float bv = -1.f; int bi = NP;
        {
            const int cstart = k & ~3;
            const int k2c    = k2 & ~3;
            const bool hi2   = (k2 & 2) != 0;
            for (int pr = wid; ; pr += NW) {
                const int r0 = k2 + 1 + 2 * pr;
                if (r0 >= NP) break;
                const int r1 = r0 + 1;
                const unsigned b0 = rowb(r0);
                const unsigned b1 = (r1 < NP) ? rowb(r1) : 0u;
                const int e0 = (r0 + 3) & ~3;
                const int e1 = (r1 < NP) ? ((r1 + 3) & ~3) : 0;
                const int emax = (e1 > e0) ? e1 : e0;
                const float tr0 = tau[r0], vr0 = v[r0];
                const float tr1 = (r1 < NP) ? tau[r1] : 0.f;
                const float vr1 = (r1 < NP) ? v[r1]   : 0.f;
                for (int cc = cstart + 4 * lane; cc < emax; cc += 128) {
                    const float4 tc = *(const float4*)&tau[cc];
                    const float4 vc = *(const float4*)&v[cc];
                    float4 x0, x1;
                    const bool a0 = cc < e0;
                    const bool a1 = cc < e1;
                    if (a0) {
                        x0 = *(const float4*)&L[b0 + cc];
                        x0.x += vr0 * tc.x - tr0 * vc.x;
                        x0.y += vr0 * tc.y - tr0 * vc.y;
                        x0.z += vr0 * tc.z - tr0 * vc.z;
                        x0.w += vr0 * tc.w - tr0 * vc.w;
                        *(float4*)&L[b0 + cc] = x0;
                    }
                    if (a1) {
                        x1 = *(const float4*)&L[b1 + cc];
                        x1.x += vr1 * tc.x - tr1 * vc.x;
                        x1.y += vr1 * tc.y - tr1 * vc.y;
                        x1.z += vr1 * tc.z - tr1 * vc.z;
                        x1.w += vr1 * tc.w - tr1 * vc.w;
                        *(float4*)&L[b1 + cc] = x1;
                    }
                    if (cc == k2c) {   // capture next pivot column entries
                        if (a0) {
                            float a = fabsf(hi2 ? x0.z : x0.x);
                            if (a > bv || (a == bv && r0 < bi)) { bv = a; bi = r0; }
                        }
                        if (a1) {
                            float a = fabsf(hi2 ? x1.z : x1.x);
                            if (a > bv || (a == bv && r1 < bi)) { bv = a; bi = r1; }
                        }
                    }
                }
            }
        }
        wred(bv, bi);
        if (lane == 0) { s_rv[wid] = bv; s_ri[wid] = bi; }
        __syncthreads();
    }

    if (tid == 0) { g_sign[m] = sign; g_logabs[m] = logabs; }
}

// ---------------------------------------------------------------------------
// Kernel 3: signed logsumexp over the 4 pfaffians per batch element
// ---------------------------------------------------------------------------
__global__ void combine_kernel(float* __restrict__ out) {
    int b = threadIdx.x;
    if (b < BATCH) {
        float la[NPFS], sg[NPFS];
        float mx = -INFINITY;
        #pragma unroll
        for (int p = 0; p < NPFS; p++) {
            la[p] = g_logabs[b * NPFS + p];
            sg[p] = g_sign[b * NPFS + p];
            mx = fmaxf(mx, la[p]);
        }
        float val = 0.f;
        #pragma unroll
        for (int p = 0; p < NPFS; p++)
            val += sg[p] * expf(la[p] - mx);
        out[b]         = (val > 0.f) ? 1.f : ((val < 0.f) ? -1.f : 0.f);
        out[BATCH + b] = mx + logf(fabsf(val));
    }
}

// ---------------------------------------------------------------------------
extern "C" void kernel_launch(void* const* d_in, const int* in_sizes, int n_in,
                              void* d_out, int out_size) {
    const float* F   = (const float*)d_in[0];   // (4, 512, 512) fp32
    const int*   idx = (const int*)  d_in[1];   // (128, 256) int32
    float*       out = (float*)d_out;           // (2, 128) fp32

    const size_t shmem = (size_t)(L_ELEMS + 2 * NP) * sizeof(float); // ~138.8 KB
    cudaFuncSetAttribute(pf_kernel, cudaFuncAttributeMaxDynamicSharedMemorySize,
                         (int)shmem);

    prep_kernel<<<(NPFS * NF * NF) / 256, 256>>>(F);
    pf_kernel<<<NMAT, NTHR, shmem>>>(idx);
    combine_kernel<<<1, 128>>>(out);
}

// round 5
// speedup vs baseline: 1.8730x; 1.0713x over previous
#include <cuda_runtime.h>
#include <math.h>

#define NPFS  4
#define NF    512
#define NP    256
#define BATCH 128
#define NMAT  (BATCH * NPFS)            // 512 matrices
#define NTHR  512
#define NW    (NTHR / 32)               // 16 warps

// padded, 16B-aligned row bases for the lower triangle
__device__ __host__ __forceinline__ unsigned rowb(int r) {
    return ((unsigned)((r * (r - 1)) / 2 + 6 * r)) & ~3u;
}
#define L_ELEMS 34176                    // >= rowb(255) + 260, mult of 4

// Scratch (__device__ globals — allocations forbidden)
__device__ float g_Ffull[NPFS * NF * NF];   // antisymmetrized F, 4 MB (L2-resident)
__device__ float g_sign[NMAT];
__device__ float g_logabs[NMAT];

// ---------------------------------------------------------------------------
// Kernel 1: F_full = 0.5 * (F - F^T)
// ---------------------------------------------------------------------------
__global__ void prep_kernel(const float* __restrict__ F) {
    int i = blockIdx.x * 256 + threadIdx.x;
    int p   = i >> 18;
    int rem = i & ((1 << 18) - 1);
    int r = rem >> 9;
    int c = rem & (NF - 1);
    float a = F[i];
    float b = F[(p << 18) + (c << 9) + r];
    g_Ffull[i] = 0.5f * (a - b);
}

__device__ __forceinline__ void wred(float& bv, int& bi) {
    #pragma unroll
    for (int off = 16; off; off >>= 1) {
        float ov = __shfl_down_sync(0xffffffffu, bv, off);
        int   oi = __shfl_down_sync(0xffffffffu, bi, off);
        if (ov > bv || (ov == bv && oi < bi)) { bv = ov; bi = oi; }
    }
}

// ---------------------------------------------------------------------------
// Kernel 2: one CTA per matrix. Lower triangle (aligned padded rows) in smem.
// Parlett-Reid, partial pivoting. Columns k+2,k+3 cached into compact arrays
// (colA/colB) during the rank-2 update; pivot scan fused with that extraction.
// Fill/swap phase reads compact arrays. 4 rows per warp in the update.
// 2 barriers per step, all hot smem ops 128-bit conflict-free.
// ---------------------------------------------------------------------------
__global__ __launch_bounds__(NTHR, 1)
void pf_kernel(const int* __restrict__ idx) {
    extern __shared__ float sm[];
    float* L    = sm;                 // [L_ELEMS]
    float* tau  = sm + L_ELEMS;       // [NP]
    float* v    = tau + NP;           // [NP]
    float* colA = v + NP;             // [NP]  cached column k   (current step)
    float* colB = colA + NP;          // [NP]  cached column k+1

    __shared__ int   s_idx[NP];
    __shared__ float s_rv[NW];
    __shared__ int   s_ri[NW];

    const int tid  = threadIdx.x;
    const int lane = tid & 31;
    const int wid  = tid >> 5;
    const int m    = blockIdx.x;
    const int b    = m >> 2;
    const int p    = m & 3;

    if (tid < NP) s_idx[tid] = idx[b * NP + tid];
    __syncthreads();

    // ---- gather (warp per row) + initial column cache + pivot scan col 0 ----
    {
        float bv = -1.f; int bi = NP;
        const float* Fp = g_Ffull + (size_t)p * (NF * NF);
        for (int r = wid; r < NP; r += NW) {
            const float* row = Fp + (size_t)s_idx[r] * NF;
            unsigned base = rowb(r);
            for (int c = lane; c < r; c += 32) {
                float val = __ldg(&row[s_idx[c]]);
                L[base + c] = val;
                if (c == 0) {
                    colA[r] = val;
                    float a = fabsf(val);
                    if (a > bv || (a == bv && r < bi)) { bv = a; bi = r; }
                }
                if (c == 1) colB[r] = val;
            }
        }
        wred(bv, bi);
        if (lane == 0) { s_rv[wid] = bv; s_ri[wid] = bi; }
    }
    __syncthreads();

    float sign = 1.f, logabs = 0.f;   // live in thread 0

    for (int k = 0; k < NP; k += 2) {
        const int p1 = k + 1;
        const int k2 = k + 2;
        const int k3 = k + 3;

        // ---- reduce the NW pivot candidates (16-lane butterfly) ----
        float pv = s_rv[lane & (NW - 1)];
        int   pi = s_ri[lane & (NW - 1)];
        #pragma unroll
        for (int off = NW / 2; off; off >>= 1) {
            float ov = __shfl_xor_sync(0xffffffffu, pv, off);
            int   oi = __shfl_xor_sync(0xffffffffu, pi, off);
            if (ov > pv || (ov == pv && oi < pi)) { pv = ov; pi = oi; }
        }
        const int kp = pi;                         // pivot row in (k, NP)
        const float piv = -colA[kp];               // post-swap A[k][k+1]
        if (tid == 0) {
            if (kp != p1)  sign = -sign;
            if (piv < 0.f) sign = -sign;
            logabs += logf(fabsf(piv));
        }

        // ---- fill tau/v (zeros at k,k+1) + live half of symmetric swap ----
        if (tid >= k && tid < NP) {
            const int t = tid;
            float tauv = 0.f, vv = 0.f;
            if (t >= k2) {
                const float rp = 1.0f / piv;
                tauv = (t == kp ? colA[p1] : colA[t]) * rp;
                if (kp != p1) {
                    if (t < kp) {
                        vv = -L[rowb(kp) + t];
                        L[rowb(kp) + t] = -colB[t];
                    } else if (t == kp) {
                        vv = -colB[kp];
                    } else {
                        vv = L[rowb(t) + kp];
                        L[rowb(t) + kp] = colB[t];
                    }
                } else {
                    vv = colB[t];
                }
            }
            tau[t] = tauv;
            v[t]   = vv;
        }
        __syncthreads();

        if (k2 >= NP) break;   // last step: no trailing update

        // ---- rank-2 update (4 rows per warp) + column cache + pivot scan ----
        float bv = -1.f; int bi = NP;
        const int cstart = k & ~3;
        for (int pr = wid; ; pr += 2 * NW) {
            const int rA0 = k3 + 2 * pr;
            if (rA0 >= NP) break;
            const int rA1 = rA0 + 1;
            const int rB0 = rA0 + 2 * NW;   // +32
            const int rB1 = rB0 + 1;
            const unsigned bA0 = rowb(rA0);
            const unsigned bA1 = (rA1 < NP) ? rowb(rA1) : 0u;
            const unsigned bB0 = (rB0 < NP) ? rowb(rB0) : 0u;
            const unsigned bB1 = (rB1 < NP) ? rowb(rB1) : 0u;
            const int eA0 = (rA0 + 3) & ~3;
            const int eA1 = (rA1 < NP) ? ((rA1 + 3) & ~3) : 0;
            const int eB0 = (rB0 < NP) ? ((rB0 + 3) & ~3) : 0;
            const int eB1 = (rB1 < NP) ? ((rB1 + 3) & ~3) : 0;
            int emax = eA0;
            if (eA1 > emax) emax = eA1;
            if (eB0 > emax) emax = eB0;
            if (eB1 > emax) emax = eB1;
            const float tA0 = tau[rA0],                 vA0 = v[rA0];
            const float tA1 = (rA1 < NP) ? tau[rA1] : 0.f, vA1 = (rA1 < NP) ? v[rA1] : 0.f;
            const float tB0 = (rB0 < NP) ? tau[rB0] : 0.f, vB0 = (rB0 < NP) ? v[rB0] : 0.f;
            const float tB1 = (rB1 < NP) ? tau[rB1] : 0.f, vB1 = (rB1 < NP) ? v[rB1] : 0.f;

            for (int cc = cstart + 4 * lane; cc < emax; cc += 128) {
                const float4 tc = *(const float4*)&tau[cc];
                const float4 vc = *(const float4*)&v[cc];
                if (cc < eA0) {
                    float4 x = *(const float4*)&L[bA0 + cc];
                    x.x += vA0 * tc.x - tA0 * vc.x;
                    x.y += vA0 * tc.y - tA0 * vc.y;
                    x.z += vA0 * tc.z - tA0 * vc.z;
                    x.w += vA0 * tc.w - tA0 * vc.w;
                    *(float4*)&L[bA0 + cc] = x;
                }
                if (cc < eA1) {
                    float4 x = *(const float4*)&L[bA1 + cc];
                    x.x += vA1 * tc.x - tA1 * vc.x;
                    x.y += vA1 * tc.y - tA1 * vc.y;
                    x.z += vA1 * tc.z - tA1 * vc.z;
                    x.w += vA1 * tc.w - tA1 * vc.w;
                    *(float4*)&L[bA1 + cc] = x;
                }
                if (cc < eB0) {
                    float4 x = *(const float4*)&L[bB0 + cc];
                    x.x += vB0 * tc.x - tB0 * vc.x;
                    x.y += vB0 * tc.y - tB0 * vc.y;
                    x.z += vB0 * tc.z - tB0 * vc.z;
                    x.w += vB0 * tc.w - tB0 * vc.w;
                    *(float4*)&L[bB0 + cc] = x;
                }
                if (cc < eB1) {
                    float4 x = *(const float4*)&L[bB1 + cc];
                    x.x += vB1 * tc.x - tB1 * vc.x;
                    x.y += vB1 * tc.y - tB1 * vc.y;
                    x.z += vB1 * tc.z - tB1 * vc.z;
                    x.w += vB1 * tc.w - tB1 * vc.w;
                    *(float4*)&L[bB1 + cc] = x;
                }
            }
            __syncwarp();
            // extract updated columns k2,k3 into colA/colB + pivot candidates
            if (lane < 4) {
                const int r = rA0 + (lane & 1) + ((lane >> 1) << 5);
                if (r < NP) {
                    float2 ab = *(const float2*)&L[rowb(r) + k2];
                    colA[r] = ab.x;      // A[r][k2]   (next step's pivot col)
                    colB[r] = ab.y;      // A[r][k3]   (padding junk for r==k3; unused)
                    float a = fabsf(ab.x);
                    if (a > bv || (a == bv && r < bi)) { bv = a; bi = r; }
                }
            }
        }
        wred(bv, bi);
        if (lane == 0) { s_rv[wid] = bv; s_ri[wid] = bi; }
        __syncthreads();
    }

    if (tid == 0) { g_sign[m] = sign; g_logabs[m] = logabs; }
}

// ---------------------------------------------------------------------------
// Kernel 3: signed logsumexp over the 4 pfaffians per batch element
// ---------------------------------------------------------------------------
__global__ void combine_kernel(float* __restrict__ out) {
    int b = threadIdx.x;
    if (b < BATCH) {
        float la[NPFS], sg[NPFS];
        float mx = -INFINITY;
        #pragma unroll
        for (int p = 0; p < NPFS; p++) {
            la[p] = g_logabs[b * NPFS + p];
            sg[p] = g_sign[b * NPFS + p];
            mx = fmaxf(mx, la[p]);
        }
        float val = 0.f;
        #pragma unroll
        for (int p = 0; p < NPFS; p++)
            val += sg[p] * expf(la[p] - mx);
        out[b]         = (val > 0.f) ? 1.f : ((val < 0.f) ? -1.f : 0.f);
        out[BATCH + b] = mx + logf(fabsf(val));
    }
}

// ---------------------------------------------------------------------------
extern "C" void kernel_launch(void* const* d_in, const int* in_sizes, int n_in,
                              void* d_out, int out_size) {
    const float* F   = (const float*)d_in[0];   // (4, 512, 512) fp32
    const int*   idx = (const int*)  d_in[1];   // (128, 256) int32
    float*       out = (float*)d_out;           // (2, 128) fp32

    const size_t shmem = (size_t)(L_ELEMS + 4 * NP) * sizeof(float); // ~140.8 KB
    cudaFuncSetAttribute(pf_kernel, cudaFuncAttributeMaxDynamicSharedMemorySize,
                         (int)shmem);

    prep_kernel<<<(NPFS * NF * NF) / 256, 256>>>(F);
    pf_kernel<<<NMAT, NTHR, shmem>>>(idx);
    combine_kernel<<<1, 128>>>(out);
}

// round 6
// speedup vs baseline: 1.8739x; 1.0004x over previous
#include <cuda_runtime.h>
#include <math.h>

#define NPFS  4
#define NF    512
#define NP    256
#define BATCH 128
#define NMAT  (BATCH * NPFS)            // 512 matrices
#define NTHR  512
#define NW    (NTHR / 32)               // 16 warps

// padded, 16B-aligned row bases for the lower triangle
__device__ __host__ __forceinline__ unsigned rowb(int r) {
    return ((unsigned)((r * (r - 1)) / 2 + 6 * r)) & ~3u;
}
#define L_ELEMS 34176                    // >= rowb(255) + 260, mult of 4

// Scratch (__device__ globals — allocations forbidden)
__device__ float g_Ffull[NPFS * NF * NF];   // antisymmetrized F, 4 MB (L2-resident)
__device__ float g_sign[NMAT];
__device__ float g_logabs[NMAT];

// ---------------------------------------------------------------------------
// Kernel 1: F_full = 0.5 * (F - F^T)
// ---------------------------------------------------------------------------
__global__ void prep_kernel(const float* __restrict__ F) {
    int i = blockIdx.x * 256 + threadIdx.x;
    int p   = i >> 18;
    int rem = i & ((1 << 18) - 1);
    int r = rem >> 9;
    int c = rem & (NF - 1);
    float a = F[i];
    float b = F[(p << 18) + (c << 9) + r];
    g_Ffull[i] = 0.5f * (a - b);
}

__device__ __forceinline__ void wred(float& bv, int& bi) {
    #pragma unroll
    for (int off = 16; off; off >>= 1) {
        float ov = __shfl_down_sync(0xffffffffu, bv, off);
        int   oi = __shfl_down_sync(0xffffffffu, bi, off);
        if (ov > bv || (ov == bv && oi < bi)) { bv = ov; bi = oi; }
    }
}

// ---------------------------------------------------------------------------
// Kernel 2: one CTA per matrix. Lower triangle (aligned padded rows) in smem.
// Parlett-Reid, partial pivoting. Columns k+2,k+3 cached into compact arrays
// (colA/colB) during the rank-2 update; pivot scan fused with that extraction.
// Fill/swap phase reads compact arrays. 4 rows per warp in the update.
// 2 barriers per step, all hot smem ops 128-bit conflict-free.
// ---------------------------------------------------------------------------
__global__ __launch_bounds__(NTHR, 1)
void pf_kernel(const int* __restrict__ idx) {
    extern __shared__ float sm[];
    float* L    = sm;                 // [L_ELEMS]
    float* tau  = sm + L_ELEMS;       // [NP]
    float* v    = tau + NP;           // [NP]
    float* colA = v + NP;             // [NP]  cached column k   (current step)
    float* colB = colA + NP;          // [NP]  cached column k+1

    __shared__ int   s_idx[NP];
    __shared__ float s_rv[NW];
    __shared__ int   s_ri[NW];

    const int tid  = threadIdx.x;
    const int lane = tid & 31;
    const int wid  = tid >> 5;
    const int m    = blockIdx.x;
    const int b    = m >> 2;
    const int p    = m & 3;

    if (tid < NP) s_idx[tid] = idx[b * NP + tid];
    __syncthreads();

    // ---- gather (warp per row) + initial column cache + pivot scan col 0 ----
    {
        float bv = -1.f; int bi = NP;
        const float* Fp = g_Ffull + (size_t)p * (NF * NF);
        for (int r = wid; r < NP; r += NW) {
            const float* row = Fp + (size_t)s_idx[r] * NF;
            unsigned base = rowb(r);
            for (int c = lane; c < r; c += 32) {
                float val = __ldg(&row[s_idx[c]]);
                L[base + c] = val;
                if (c == 0) {
                    colA[r] = val;
                    float a = fabsf(val);
                    if (a > bv || (a == bv && r < bi)) { bv = a; bi = r; }
                }
                if (c == 1) colB[r] = val;
            }
        }
        wred(bv, bi);
        if (lane == 0) { s_rv[wid] = bv; s_ri[wid] = bi; }
    }
    __syncthreads();

    float sign = 1.f, logabs = 0.f;   // live in thread 0

    for (int k = 0; k < NP; k += 2) {
        const int p1 = k + 1;
        const int k2 = k + 2;
        const int k3 = k + 3;

        // ---- reduce the NW pivot candidates (16-lane butterfly) ----
        float pv = s_rv[lane & (NW - 1)];
        int   pi = s_ri[lane & (NW - 1)];
        #pragma unroll
        for (int off = NW / 2; off; off >>= 1) {
            float ov = __shfl_xor_sync(0xffffffffu, pv, off);
            int   oi = __shfl_xor_sync(0xffffffffu, pi, off);
            if (ov > pv || (ov == pv && oi < pi)) { pv = ov; pi = oi; }
        }
        const int kp = pi;                         // pivot row in (k, NP)
        const float piv = -colA[kp];               // post-swap A[k][k+1]
        if (tid == 0) {
            if (kp != p1)  sign = -sign;
            if (piv < 0.f) sign = -sign;
            logabs += logf(fabsf(piv));
        }

        // ---- fill tau/v (zeros at k,k+1) + live half of symmetric swap ----
        if (tid >= k && tid < NP) {
            const int t = tid;
            float tauv = 0.f, vv = 0.f;
            if (t >= k2) {
                const float rp = 1.0f / piv;
                tauv = (t == kp ? colA[p1] : colA[t]) * rp;
                if (kp != p1) {
                    if (t < kp) {
                        vv = -L[rowb(kp) + t];
                        L[rowb(kp) + t] = -colB[t];
                    } else if (t == kp) {
                        vv = -colB[kp];
                    } else {
                        vv = L[rowb(t) + kp];
                        L[rowb(t) + kp] = colB[t];
                    }
                } else {
                    vv = colB[t];
                }
            }
            tau[t] = tauv;
            v[t]   = vv;
        }
        __syncthreads();

        if (k2 >= NP) break;   // last step: no trailing update

        // ---- rank-2 update (4 rows per warp) + column cache + pivot scan ----
        float bv = -1.f; int bi = NP;
        const int cstart = k & ~3;
        for (int pr = wid; ; pr += 2 * NW) {
            const int rA0 = k3 + 2 * pr;
            if (rA0 >= NP) break;
            const int rA1 = rA0 + 1;
            const int rB0 = rA0 + 2 * NW;   // +32
            const int rB1 = rB0 + 1;
            const unsigned bA0 = rowb(rA0);
            const unsigned bA1 = (rA1 < NP) ? rowb(rA1) : 0u;
            const unsigned bB0 = (rB0 < NP) ? rowb(rB0) : 0u;
            const unsigned bB1 = (rB1 < NP) ? rowb(rB1) : 0u;
            const int eA0 = (rA0 + 3) & ~3;
            const int eA1 = (rA1 < NP) ? ((rA1 + 3) & ~3) : 0;
            const int eB0 = (rB0 < NP) ? ((rB0 + 3) & ~3) : 0;
            const int eB1 = (rB1 < NP) ? ((rB1 + 3) & ~3) : 0;
            int emax = eA0;
            if (eA1 > emax) emax = eA1;
            if (eB0 > emax) emax = eB0;
            if (eB1 > emax) emax = eB1;
            const float tA0 = tau[rA0],                 vA0 = v[rA0];
            const float tA1 = (rA1 < NP) ? tau[rA1] : 0.f, vA1 = (rA1 < NP) ? v[rA1] : 0.f;
            const float tB0 = (rB0 < NP) ? tau[rB0] : 0.f, vB0 = (rB0 < NP) ? v[rB0] : 0.f;
            const float tB1 = (rB1 < NP) ? tau[rB1] : 0.f, vB1 = (rB1 < NP) ? v[rB1] : 0.f;

            for (int cc = cstart + 4 * lane; cc < emax; cc += 128) {
                const float4 tc = *(const float4*)&tau[cc];
                const float4 vc = *(const float4*)&v[cc];
                if (cc < eA0) {
                    float4 x = *(const float4*)&L[bA0 + cc];
                    x.x += vA0 * tc.x - tA0 * vc.x;
                    x.y += vA0 * tc.y - tA0 * vc.y;
                    x.z += vA0 * tc.z - tA0 * vc.z;
                    x.w += vA0 * tc.w - tA0 * vc.w;
                    *(float4*)&L[bA0 + cc] = x;
                }
                if (cc < eA1) {
                    float4 x = *(const float4*)&L[bA1 + cc];
                    x.x += vA1 * tc.x - tA1 * vc.x;
                    x.y += vA1 * tc.y - tA1 * vc.y;
                    x.z += vA1 * tc.z - tA1 * vc.z;
                    x.w += vA1 * tc.w - tA1 * vc.w;
                    *(float4*)&L[bA1 + cc] = x;
                }
                if (cc < eB0) {
                    float4 x = *(const float4*)&L[bB0 + cc];
                    x.x += vB0 * tc.x - tB0 * vc.x;
                    x.y += vB0 * tc.y - tB0 * vc.y;
                    x.z += vB0 * tc.z - tB0 * vc.z;
                    x.w += vB0 * tc.w - tB0 * vc.w;
                    *(float4*)&L[bB0 + cc] = x;
                }
                if (cc < eB1) {
                    float4 x = *(const float4*)&L[bB1 + cc];
                    x.x += vB1 * tc.x - tB1 * vc.x;
                    x.y += vB1 * tc.y - tB1 * vc.y;
                    x.z += vB1 * tc.z - tB1 * vc.z;
                    x.w += vB1 * tc.w - tB1 * vc.w;
                    *(float4*)&L[bB1 + cc] = x;
                }
            }
            __syncwarp();
            // extract updated columns k2,k3 into colA/colB + pivot candidates
            if (lane < 4) {
                const int r = rA0 + (lane & 1) + ((lane >> 1) << 5);
                if (r < NP) {
                    float2 ab = *(const float2*)&L[rowb(r) + k2];
                    colA[r] = ab.x;      // A[r][k2]   (next step's pivot col)
                    colB[r] = ab.y;      // A[r][k3]   (padding junk for r==k3; unused)
                    float a = fabsf(ab.x);
                    if (a > bv || (a == bv && r < bi)) { bv = a; bi = r; }
                }
            }
        }
        wred(bv, bi);
        if (lane == 0) { s_rv[wid] = bv; s_ri[wid] = bi; }
        __syncthreads();
    }

    if (tid == 0) { g_sign[m] = sign; g_logabs[m] = logabs; }
}

// ---------------------------------------------------------------------------
// Kernel 3: signed logsumexp over the 4 pfaffians per batch element
// ---------------------------------------------------------------------------
__global__ void combine_kernel(float* __restrict__ out) {
    int b = threadIdx.x;
    if (b < BATCH) {
        float la[NPFS], sg[NPFS];
        float mx = -INFINITY;
        #pragma unroll
        for (int p = 0; p < NPFS; p++) {
            la[p] = g_logabs[b * NPFS + p];
            sg[p] = g_sign[b * NPFS + p];
            mx = fmaxf(mx, la[p]);
        }
        float val = 0.f;
        #pragma unroll
        for (int p = 0; p < NPFS; p++)
            val += sg[p] * expf(la[p] - mx);
        out[b]         = (val > 0.f) ? 1.f : ((val < 0.f) ? -1.f : 0.f);
        out[BATCH + b] = mx + logf(fabsf(val));
    }
}

// ---------------------------------------------------------------------------
extern "C" void kernel_launch(void* const* d_in, const int* in_sizes, int n_in,
                              void* d_out, int out_size) {
    const float* F   = (const float*)d_in[0];   // (4, 512, 512) fp32
    const int*   idx = (const int*)  d_in[1];   // (128, 256) int32
    float*       out = (float*)d_out;           // (2, 128) fp32

    const size_t shmem = (size_t)(L_ELEMS + 4 * NP) * sizeof(float); // ~140.8 KB
    cudaFuncSetAttribute(pf_kernel, cudaFuncAttributeMaxDynamicSharedMemorySize,
                         (int)shmem);

    prep_kernel<<<(NPFS * NF * NF) / 256, 256>>>(F);
    pf_kernel<<<NMAT, NTHR, shmem>>>(idx);
    combine_kernel<<<1, 128>>>(out);
}

// round 7
// speedup vs baseline: 2.3889x; 1.2748x over previous
#include <cuda_runtime.h>
#include <math.h>

#define NPFS  4
#define NF    512
#define NP    256
#define BATCH 128
#define NMAT  (BATCH * NPFS)            // 512 matrices
#define NTHR  512
#define NW    (NTHR / 32)               // 16 warps

// padded, 16B-aligned row bases for the lower triangle
__device__ __host__ __forceinline__ unsigned rowb(int r) {
    return ((unsigned)((r * (r - 1)) / 2 + 6 * r)) & ~3u;
}
#define L_ELEMS 34176                    // >= rowb(255) + 260, mult of 4

// Scratch (__device__ globals — allocations forbidden)
__device__ float g_Ffull[NPFS * NF * NF];   // antisymmetrized F, 4 MB (L2-resident)
__device__ float g_sign[NMAT];
__device__ float g_logabs[NMAT];

// ---------------------------------------------------------------------------
// Kernel 1: F_full = 0.5 * (F - F^T)
// ---------------------------------------------------------------------------
__global__ void prep_kernel(const float* __restrict__ F) {
    int i = blockIdx.x * 256 + threadIdx.x;
    int p   = i >> 18;
    int rem = i & ((1 << 18) - 1);
    int r = rem >> 9;
    int c = rem & (NF - 1);
    float a = F[i];
    float b = F[(p << 18) + (c << 9) + r];
    g_Ffull[i] = 0.5f * (a - b);
}

__device__ __forceinline__ void wred(float& bv, int& bi) {
    #pragma unroll
    for (int off = 16; off; off >>= 1) {
        float ov = __shfl_down_sync(0xffffffffu, bv, off);
        int   oi = __shfl_down_sync(0xffffffffu, bi, off);
        if (ov > bv || (ov == bv && oi < bi)) { bv = ov; bi = oi; }
    }
}

// ---------------------------------------------------------------------------
// Kernel 2: one CTA per matrix. Lower triangle (padded rows) in smem.
// Parlett-Reid with partial pivoting, TWO elimination steps fused into ONE
// trailing rank-4 pass. Step-2's swap is composed into (tau1,v1) by entry
// permutation; L swap writes use raw (pre-update-1) values so the fused pass
// adds update-1 on top correctly. Updated columns k+2,k+3 built in O(n).
// ---------------------------------------------------------------------------
__global__ __launch_bounds__(NTHR, 1)
void pf_kernel(const int* __restrict__ idx) {
    extern __shared__ float sm[];
    float* L     = sm;                  // [L_ELEMS]
    float* tau1  = sm + L_ELEMS;        // [NP]
    float* v1    = tau1 + NP;           // [NP]
    float* tau2  = v1 + NP;             // [NP]
    float* v2    = tau2 + NP;           // [NP]
    float* tau1p = v2 + NP;             // [NP]  swap-b-permuted tau1
    float* v1p   = tau1p + NP;          // [NP]
    float* colA  = v1p + NP;            // [NP]  current column k   (updated)
    float* colB  = colA + NP;           // [NP]  current column k+1 (updated)
    float* colBr = colB + NP;           // [NP]  raw column k+3 (pre-update-1)

    __shared__ int   s_idx[NP];
    __shared__ float s_rv[NW];
    __shared__ int   s_ri[NW];

    const int tid  = threadIdx.x;
    const int lane = tid & 31;
    const int wid  = tid >> 5;
    const int m    = blockIdx.x;
    const int b    = m >> 2;
    const int p    = m & 3;

    if (tid < NP) s_idx[tid] = idx[b * NP + tid];
    __syncthreads();

    // ---- gather (warp per row) + initial column cache + pivot scan col 0 ----
    {
        float bv = -1.f; int bi = NP;
        const float* Fp = g_Ffull + (size_t)p * (NF * NF);
        for (int r = wid; r < NP; r += NW) {
            const float* row = Fp + (size_t)s_idx[r] * NF;
            unsigned base = rowb(r);
            for (int c = lane; c < r; c += 32) {
                float val = __ldg(&row[s_idx[c]]);
                L[base + c] = val;
                if (c == 0) {
                    colA[r] = val;
                    float a = fabsf(val);
                    if (a > bv || (a == bv && r < bi)) { bv = a; bi = r; }
                }
                if (c == 1) colB[r] = val;
            }
        }
        wred(bv, bi);
        if (lane == 0) { s_rv[wid] = bv; s_ri[wid] = bi; }
    }
    __syncthreads();

    float sign = 1.f, logabs = 0.f;   // live in thread 0

    for (int k = 0; k < NP; k += 4) {
        const int p1 = k + 1;
        const int k2 = k + 2;
        const int k3 = k + 3;
        const int k4 = k + 4;
        const int k5 = k + 5;

        // ---- phase A: reduce pivot-a candidates (16-lane butterfly) ----
        float pv = s_rv[lane & (NW - 1)];
        int   pi = s_ri[lane & (NW - 1)];
        #pragma unroll
        for (int off = NW / 2; off; off >>= 1) {
            float ov = __shfl_xor_sync(0xffffffffu, pv, off);
            int   oi = __shfl_xor_sync(0xffffffffu, pi, off);
            if (ov > pv || (ov == pv && oi < pi)) { pv = ov; pi = oi; }
        }
        const int   kp1  = pi;                 // pivot-a row in (k, NP)
        const float piv1 = -colA[kp1];         // post-swap A[k][k+1]
        if (tid == 0) {
            if (kp1 != p1)  sign = -sign;
            if (piv1 < 0.f) sign = -sign;
            logabs += logf(fabsf(piv1));
        }

        // ---- phase B: tau1/v1 fill + live half of swap-a (writes A_a into L) ----
        if (tid >= k2 && tid < NP) {
            const int t = tid;
            const float rp = 1.0f / piv1;
            float ta = (t == kp1 ? colA[p1] : colA[t]) * rp;
            float vv;
            if (kp1 != p1) {
                if (t < kp1) {
                    vv = -L[rowb(kp1) + t];
                    L[rowb(kp1) + t] = -colB[t];
                } else if (t == kp1) {
                    vv = -colB[kp1];
                } else {
                    vv = L[rowb(t) + kp1];
                    L[rowb(t) + kp1] = colB[t];
                }
            } else {
                vv = colB[t];
            }
            tau1[t] = ta;
            v1[t]   = vv;
        }
        __syncthreads();

        // ---- phase C: updated columns k2,k3 (O(n)) + raw col k3 + pivot-b scan ----
        {
            float bv = -1.f; int bi = NP;
            if (tid >= k3 && tid < NP) {
                const int t = tid;
                float2 raw = *(const float2*)&L[rowb(t) + k2];
                const float t1 = tau1[t], w1 = v1[t];
                const float t1k2 = tau1[k2], v1k2 = v1[k2];
                const float t1k3 = tau1[k3], v1k3 = v1[k3];
                float ca = raw.x + w1 * t1k2 - t1 * v1k2;   // A'[t][k2]
                float cb = raw.y + w1 * t1k3 - t1 * v1k3;   // A'[t][k3]
                colA[t]  = ca;
                colB[t]  = cb;
                colBr[t] = raw.y;                            // raw A_a[t][k3]
                bv = fabsf(ca); bi = t;
            }
            wred(bv, bi);
            if (lane == 0) { s_rv[wid] = bv; s_ri[wid] = bi; }
        }
        __syncthreads();

        // ---- phase D: pivot-b reduce; tau2/v2 fill + swap-b (raw writes);
        //      permuted tau1p/v1p ----
        pv = s_rv[lane & (NW - 1)];
        pi = s_ri[lane & (NW - 1)];
        #pragma unroll
        for (int off = NW / 2; off; off >>= 1) {
            float ov = __shfl_xor_sync(0xffffffffu, pv, off);
            int   oi = __shfl_xor_sync(0xffffffffu, pi, off);
            if (ov > pv || (ov == pv && oi < pi)) { pv = ov; pi = oi; }
        }
        const int   kp2  = pi;                 // pivot-b row in (k2, NP)
        const float piv2 = -colA[kp2];         // post-swap A'[k2][k3]
        if (tid == 0) {
            if (kp2 != k3)  sign = -sign;
            if (piv2 < 0.f) sign = -sign;
            logabs += logf(fabsf(piv2));
        }
        if (tid >= k4 && tid < NP) {
            const int t = tid;
            const float rp2 = 1.0f / piv2;
            float ta = (t == kp2 ? colA[k3] : colA[t]) * rp2;
            float vv;
            if (kp2 != k3) {
                if (t < kp2) {
                    // A'[kp2][t] = raw + update-1 correction
                    vv = -(L[rowb(kp2) + t] + v1[kp2] * tau1[t] - tau1[kp2] * v1[t]);
                    L[rowb(kp2) + t] = -colBr[t];            // raw swap write
                } else if (t == kp2) {
                    vv = -colB[kp2];                         // -A'[kp2][k3]
                } else {
                    vv = L[rowb(t) + kp2] + v1[t] * tau1[kp2] - tau1[t] * v1[kp2];
                    L[rowb(t) + kp2] = colBr[t];             // raw swap write
                }
            } else {
                vv = colB[t];
            }
            tau2[t] = ta;
            v2[t]   = vv;
            tau1p[t] = (t == kp2) ? tau1[k3] : tau1[t];      // P-permuted step-1 vectors
            v1p[t]   = (t == kp2) ? v1[k3]   : v1[t];
        }
        __syncthreads();

        // ---- phase E: ONE rank-4 trailing pass over r,c >= k4 (+extraction) ----
        if (k4 < NP) {
            float bv = -1.f; int bi = NP;
            const int cstart = k4;   // k % 4 == 0 -> 16B aligned, no dead cols
            for (int pr = wid; ; pr += 2 * NW) {
                const int rA0 = k5 + 2 * pr;
                if (rA0 >= NP) break;
                const int rA1 = rA0 + 1;
                const int rB0 = rA0 + 2 * NW;
                const int rB1 = rB0 + 1;
                const unsigned bA0 = rowb(rA0);
                const unsigned bA1 = (rA1 < NP) ? rowb(rA1) : 0u;
                const unsigned bB0 = (rB0 < NP) ? rowb(rB0) : 0u;
                const unsigned bB1 = (rB1 < NP) ? rowb(rB1) : 0u;
                const int eA0 = (rA0 + 3) & ~3;
                const int eA1 = (rA1 < NP) ? ((rA1 + 3) & ~3) : 0;
                const int eB0 = (rB0 < NP) ? ((rB0 + 3) & ~3) : 0;
                const int eB1 = (rB1 < NP) ? ((rB1 + 3) & ~3) : 0;
                int emax = eA0;
                if (eA1 > emax) emax = eA1;
                if (eB0 > emax) emax = eB0;
                if (eB1 > emax) emax = eB1;
                const float tA0 = tau1p[rA0], wA0 = v1p[rA0];
                const float uA0 = tau2[rA0],  zA0 = v2[rA0];
                const float tA1 = (rA1 < NP) ? tau1p[rA1] : 0.f, wA1 = (rA1 < NP) ? v1p[rA1] : 0.f;
                const float uA1 = (rA1 < NP) ? tau2[rA1]  : 0.f, zA1 = (rA1 < NP) ? v2[rA1]  : 0.f;
                const float tB0 = (rB0 < NP) ? tau1p[rB0] : 0.f, wB0 = (rB0 < NP) ? v1p[rB0] : 0.f;
                const float uB0 = (rB0 < NP) ? tau2[rB0]  : 0.f, zB0 = (rB0 < NP) ? v2[rB0]  : 0.f;
                const float tB1 = (rB1 < NP) ? tau1p[rB1] : 0.f, wB1 = (rB1 < NP) ? v1p[rB1] : 0.f;
                const float uB1 = (rB1 < NP) ? tau2[rB1]  : 0.f, zB1 = (rB1 < NP) ? v2[rB1]  : 0.f;

                for (int cc = cstart + 4 * lane; cc < emax; cc += 128) {
                    const float4 t1c = *(const float4*)&tau1p[cc];
                    const float4 w1c = *(const float4*)&v1p[cc];
                    const float4 t2c = *(const float4*)&tau2[cc];
                    const float4 w2c = *(const float4*)&v2[cc];

                    #define ROW_UPD(BX, EX, TR, WR, UR, ZR, RX)                          \
                    if (cc < EX) {                                                       \
                        float4 x = *(const float4*)&L[BX + cc];                          \
                        x.x += WR * t1c.x - TR * w1c.x + ZR * t2c.x - UR * w2c.x;        \
                        x.y += WR * t1c.y - TR * w1c.y + ZR * t2c.y - UR * w2c.y;        \
                        x.z += WR * t1c.z - TR * w1c.z + ZR * t2c.z - UR * w2c.z;        \
                        x.w += WR * t1c.w - TR * w1c.w + ZR * t2c.w - UR * w2c.w;        \
                        *(float4*)&L[BX + cc] = x;                                       \
                        if (cc == cstart) {                                              \
                            colA[RX] = x.x; colB[RX] = x.y;                              \
                            float a_ = fabsf(x.x);                                       \
                            if (a_ > bv || (a_ == bv && RX < bi)) { bv = a_; bi = RX; }  \
                        }                                                                \
                    }

                    ROW_UPD(bA0, eA0, tA0, wA0, uA0, zA0, rA0)
                    ROW_UPD(bA1, eA1, tA1, wA1, uA1, zA1, rA1)
                    ROW_UPD(bB0, eB0, tB0, wB0, uB0, zB0, rB0)
                    ROW_UPD(bB1, eB1, tB1, wB1, uB1, zB1, rB1)
                    #undef ROW_UPD
                }
            }
            wred(bv, bi);
            if (lane == 0) { s_rv[wid] = bv; s_ri[wid] = bi; }
        }
        __syncthreads();
    }

    if (tid == 0) { g_sign[m] = sign; g_logabs[m] = logabs; }
}

// ---------------------------------------------------------------------------
// Kernel 3: signed logsumexp over the 4 pfaffians per batch element
// ---------------------------------------------------------------------------
__global__ void combine_kernel(float* __restrict__ out) {
    int b = threadIdx.x;
    if (b < BATCH) {
        float la[NPFS], sg[NPFS];
        float mx = -INFINITY;
        #pragma unroll
        for (int p = 0; p < NPFS; p++) {
            la[p] = g_logabs[b * NPFS + p];
            sg[p] = g_sign[b * NPFS + p];
            mx = fmaxf(mx, la[p]);
        }
        float val = 0.f;
        #pragma unroll
        for (int p = 0; p < NPFS; p++)
            val += sg[p] * expf(la[p] - mx);
        out[b]         = (val > 0.f) ? 1.f : ((val < 0.f) ? -1.f : 0.f);
        out[BATCH + b] = mx + logf(fabsf(val));
    }
}

// ---------------------------------------------------------------------------
extern "C" void kernel_launch(void* const* d_in, const int* in_sizes, int n_in,
                              void* d_out, int out_size) {
    const float* F   = (const float*)d_in[0];   // (4, 512, 512) fp32
    const int*   idx = (const int*)  d_in[1];   // (128, 256) int32
    float*       out = (float*)d_out;           // (2, 128) fp32

    const size_t shmem = (size_t)(L_ELEMS + 9 * NP) * sizeof(float); // ~142.5 KB
    cudaFuncSetAttribute(pf_kernel, cudaFuncAttributeMaxDynamicSharedMemorySize,
                         (int)shmem);

    prep_kernel<<<(NPFS * NF * NF) / 256, 256>>>(F);
    pf_kernel<<<NMAT, NTHR, shmem>>>(idx);
    combine_kernel<<<1, 128>>>(out);
}